// round 1
// baseline (speedup 1.0000x reference)
#include <cuda_runtime.h>
#include <cuda_bf16.h>
#include <cstdint>

// Problem constants (fixed by the registry problem).
#define D_DIM   128
#define NPOS    512
#define K_DIM   2048
#define R_MAX   49152    // B*H*Q = 2*12*2048

// 100 MB scratch for the interpolation tables (one 512-entry row per (b,h,q)).
__device__ float g_logits[(size_t)R_MAX * NPOS];

// ---------------------------------------------------------------------------
// Packed fp32x2 FMA (full-rate fp32 on Blackwell; 3-reg FFMA is half-rate).
// ---------------------------------------------------------------------------
__device__ __forceinline__ void ffma2(unsigned long long& d,
                                      unsigned long long a,
                                      unsigned long long b) {
    asm("fma.rn.f32x2 %0, %1, %2, %0;" : "+l"(d) : "l"(a), "l"(b));
}

__device__ __forceinline__ float f2lo(unsigned long long u) {
    return __uint_as_float((unsigned)(u & 0xffffffffull));
}
__device__ __forceinline__ float f2hi(unsigned long long u) {
    return __uint_as_float((unsigned)(u >> 32));
}

// ---------------------------------------------------------------------------
// Kernel A: C[R, 512] = Q[R, 128] @ P[128, 512]   (fp32, FFMA2 inner loop)
// Tile: BM=64 x BN=64, 256 threads (16x16), TM=4 x TN=4 per thread.
// smem: As = A-tile stored [k][m] (XOR-f4 swizzled), 32 KB
//       Bs = B-tile stored [k][n] with every value DUPLICATED (b,b), 64 KB
// Accumulators are f32x2 pairs along M, so the A pairs come straight out of
// an LDS.128 and the B (b,b) pairs come straight out of the dup layout:
// inner loop per k per thread = 3 LDS.128 + 8 FFMA2 (fma-pipe bound).
// ---------------------------------------------------------------------------
__global__ __launch_bounds__(256, 2)
void cope_gemm_kernel(const float* __restrict__ A,   // [R,128]
                      const float* __restrict__ P,   // [128,512]
                      int R) {
    extern __shared__ float smem[];
    float* As = smem;              // 128 * 64 floats
    float* Bs = smem + 128 * 64;   // 128 * 128 floats (dup)

    const int tid = threadIdx.x;
    const int tx = tid & 15;       // 0..15  -> n sub-tile
    const int ty = tid >> 4;       // 0..15  -> m sub-tile
    const int r0 = blockIdx.y * 64;
    const int n0 = blockIdx.x * 64;

    // ---- load A tile (64 rows x 128 k), transpose into As[k][m] swizzled ----
    #pragma unroll
    for (int i = 0; i < 8; i++) {
        int idx = tid + i * 256;          // 0..2047 float4s
        int m   = idx >> 5;               // 0..63
        int k4  = idx & 31;               // float4 index along k
        float4 v = *(const float4*)(A + (size_t)(r0 + m) * D_DIM + k4 * 4);
        int sw = (((m >> 2) ^ (k4 & 15)) << 2) | (m & 3);  // swizzled column
        As[(k4 * 4 + 0) * 64 + sw] = v.x;
        As[(k4 * 4 + 1) * 64 + sw] = v.y;
        As[(k4 * 4 + 2) * 64 + sw] = v.z;
        As[(k4 * 4 + 3) * 64 + sw] = v.w;
    }

    // ---- load B tile (128 k x 64 n) with duplication: Bs[k][2j]=Bs[k][2j+1]=b ----
    #pragma unroll
    for (int i = 0; i < 8; i++) {
        int idx = tid + i * 256;          // 0..2047 float4s
        int k   = idx >> 4;               // 0..127
        int n4  = idx & 15;               // float4 index along n
        float4 v = *(const float4*)(P + (size_t)k * NPOS + n0 + n4 * 4);
        float* dst = &Bs[k * 128 + n4 * 8];
        dst[0] = v.x; dst[1] = v.x;
        dst[2] = v.y; dst[3] = v.y;
        dst[4] = v.z; dst[5] = v.z;
        dst[6] = v.w; dst[7] = v.w;
    }
    __syncthreads();

    // ---- main loop ----
    unsigned long long acc[2][4];
    #pragma unroll
    for (int i = 0; i < 2; i++)
        #pragma unroll
        for (int j = 0; j < 4; j++) acc[i][j] = 0ull;   // (+0.f, +0.f)

    #pragma unroll 4
    for (int k = 0; k < 128; k++) {
        float4 a = *(const float4*)&As[k * 64 + ((ty ^ ((k >> 2) & 15)) << 2)];
        unsigned long long a01, a23;
        a01 = ((const unsigned long long*)&a)[0];   // (a[m0], a[m0+1])
        a23 = ((const unsigned long long*)&a)[1];   // (a[m0+2], a[m0+3])
        float4 b0 = *(const float4*)&Bs[k * 128 + tx * 8];      // (n0,n0,n1,n1)
        float4 b1 = *(const float4*)&Bs[k * 128 + tx * 8 + 4];  // (n2,n2,n3,n3)
        unsigned long long bb0 = ((const unsigned long long*)&b0)[0];
        unsigned long long bb1 = ((const unsigned long long*)&b0)[1];
        unsigned long long bb2 = ((const unsigned long long*)&b1)[0];
        unsigned long long bb3 = ((const unsigned long long*)&b1)[1];
        ffma2(acc[0][0], a01, bb0);
        ffma2(acc[0][1], a01, bb1);
        ffma2(acc[0][2], a01, bb2);
        ffma2(acc[0][3], a01, bb3);
        ffma2(acc[1][0], a23, bb0);
        ffma2(acc[1][1], a23, bb1);
        ffma2(acc[1][2], a23, bb2);
        ffma2(acc[1][3], a23, bb3);
    }

    // ---- epilogue: rows r0 + ty*4 + m, cols n0 + tx*4 .. +3 ----
    #pragma unroll
    for (int m = 0; m < 4; m++) {
        int m2 = m >> 1;
        float4 o;
        if ((m & 1) == 0) {
            o.x = f2lo(acc[m2][0]); o.y = f2lo(acc[m2][1]);
            o.z = f2lo(acc[m2][2]); o.w = f2lo(acc[m2][3]);
        } else {
            o.x = f2hi(acc[m2][0]); o.y = f2hi(acc[m2][1]);
            o.z = f2hi(acc[m2][2]); o.w = f2hi(acc[m2][3]);
        }
        *(float4*)(g_logits + (size_t)(r0 + ty * 4 + m) * NPOS + n0 + tx * 4) = o;
    }
    (void)R;
}

// ---------------------------------------------------------------------------
// Kernel B: per (b,h,q) row — sigmoid, reversed cumsum, clamp, interp gather.
// 1 block (256 threads) per row; thread t owns contiguous keys [t*8, t*8+8).
// ---------------------------------------------------------------------------
__global__ __launch_bounds__(256)
void cope_gather_kernel(const float* __restrict__ attn,   // [R,2048]
                        const int*   __restrict__ nposp,
                        float*       __restrict__ out) {  // [R,2048]
    __shared__ float tab[NPOS];
    __shared__ float wsum[8];

    const int row = blockIdx.x;
    const int tid = threadIdx.x;
    const int lane = tid & 31;
    const int wid  = tid >> 5;

    // stage this row's interpolation table in smem
    const float* trow = g_logits + (size_t)row * NPOS;
    tab[tid]       = trow[tid];
    tab[tid + 256] = trow[tid + 256];

    // load 8 attn logits, sigmoid
    const float* arow = attn + (size_t)row * K_DIM + tid * 8;
    float4 v0 = *(const float4*)(arow);
    float4 v1 = *(const float4*)(arow + 4);
    float g[8];
    g[0] = v0.x; g[1] = v0.y; g[2] = v0.z; g[3] = v0.w;
    g[4] = v1.x; g[5] = v1.y; g[6] = v1.z; g[7] = v1.w;
    #pragma unroll
    for (int j = 0; j < 8; j++)
        g[j] = 1.0f / (1.0f + __expf(-g[j]));

    // reversed (suffix) cumsum inside the 8-element chunk
    float ls[8];
    ls[7] = g[7];
    #pragma unroll
    for (int j = 6; j >= 0; j--) ls[j] = g[j] + ls[j + 1];
    float csum = ls[0];                  // chunk total

    // warp inclusive scan of chunk totals (forward order)
    float v = csum;
    #pragma unroll
    for (int d = 1; d < 32; d <<= 1) {
        float t = __shfl_up_sync(0xffffffffu, v, d);
        if (lane >= d) v += t;
    }
    if (lane == 31) wsum[wid] = v;
    __syncthreads();

    float wpre = 0.0f, total = 0.0f;
    #pragma unroll
    for (int w = 0; w < 8; w++) {
        float x = wsum[w];
        total += x;
        if (w < wid) wpre += x;
    }
    float incl   = wpre + v;             // inclusive prefix of chunk totals
    float offset = total - incl;         // sum of all chunks AFTER this one

    const int   npm   = *nposp - 1;      // 511
    const float npmf  = (float)npm;

    float oo[8];
    #pragma unroll
    for (int j = 0; j < 8; j++) {
        float p  = offset + ls[j];       // reversed inclusive cumsum at key k
        p = fminf(p, npmf);
        float pf = floorf(p);
        float w  = p - pf;
        int fi = (int)pf;
        int ci = fi + 1;
        if (ci > npm) ci = npm;
        float tf = tab[fi];
        float tc = tab[ci];
        oo[j] = tc * w + tf * (1.0f - w);
    }

    float* orow = out + (size_t)row * K_DIM + tid * 8;
    *(float4*)(orow)     = make_float4(oo[0], oo[1], oo[2], oo[3]);
    *(float4*)(orow + 4) = make_float4(oo[4], oo[5], oo[6], oo[7]);
}

// ---------------------------------------------------------------------------
extern "C" void kernel_launch(void* const* d_in, const int* in_sizes, int n_in,
                              void* d_out, int out_size) {
    const float* q    = (const float*)d_in[0];   // [B,H,Q,D]
    const float* attn = (const float*)d_in[1];   // [B,H,Q,K]
    const float* pe   = (const float*)d_in[2];   // [1,D,NPOS]
    const int*   npos = (const int*)d_in[3];
    float*       out  = (float*)d_out;

    const int R = in_sizes[0] / D_DIM;           // 49152

    // GEMM: logits tables
    static const size_t smem_bytes = (128 * 64 + 128 * 128) * sizeof(float); // 96 KB
    cudaFuncSetAttribute(cope_gemm_kernel,
                         cudaFuncAttributeMaxDynamicSharedMemorySize,
                         (int)smem_bytes);
    dim3 gA(NPOS / 64, R / 64);
    cope_gemm_kernel<<<gA, 256, smem_bytes>>>(q, pe, R);

    // fused sigmoid + reversed-scan + interpolated gather
    cope_gather_kernel<<<R, 256>>>(attn, npos, out);

    (void)n_in; (void)out_size;
}

// round 3
// speedup vs baseline: 2.0898x; 2.0898x over previous
#include <cuda_runtime.h>
#include <cuda_bf16.h>
#include <cstdint>

#define D_DIM   128
#define NPOS    512
#define K_DIM   2048
#define R_MAX   49152    // B*H*Q = 2*12*2048

// 100 MB scratch for the interpolation tables (one 512-entry row per (b,h,q)).
__device__ float g_logits[(size_t)R_MAX * NPOS];

// ---------------------------------------------------------------------------
// mma.sync m16n8k16 row.col f32.bf16.bf16.f32  (sm_80+, runs on tensor pipe)
// ---------------------------------------------------------------------------
__device__ __forceinline__ void mma_bf16(float* d, const uint32_t* a, const uint32_t* b) {
    asm volatile(
        "mma.sync.aligned.m16n8k16.row.col.f32.bf16.bf16.f32 "
        "{%0,%1,%2,%3}, {%4,%5,%6,%7}, {%8,%9}, {%0,%1,%2,%3};"
        : "+f"(d[0]), "+f"(d[1]), "+f"(d[2]), "+f"(d[3])
        : "r"(a[0]), "r"(a[1]), "r"(a[2]), "r"(a[3]), "r"(b[0]), "r"(b[1]));
}

__device__ __forceinline__ uint32_t pack_bf16(float a, float b) {
    __nv_bfloat162 t = __floats2bfloat162_rn(a, b);   // .x = a (low half)
    return *reinterpret_cast<uint32_t*>(&t);
}

// ============================================================================
// Kernel A: C[R,512] = Q[R,128] @ P[128,512], bf16x3 split precision mma.sync.
// Block: 128x128 tile, 256 threads, 8 warps (4 M x 2 N), warp tile m32 x n64.
// smem: Ahi/Alo as [m][k] (128x136 bf16), Bhi/Blo as [n][k] (128x136 bf16).
// Row stride 136 bf16 = 272 B -> word-bank = row*4 + t: conflict-free frags.
// ============================================================================
#define SA_STR_B  272           // bytes per smem row (136 bf16)
#define SM_A_HI   0
#define SM_A_LO   34816         // 128*272
#define SM_B_HI   69632
#define SM_B_LO   104448
#define SM_TOTAL  139264

__global__ __launch_bounds__(256, 1)
void cope_gemm_mma(const float* __restrict__ Q,   // [R,128]
                   const float* __restrict__ P) { // [128,512]
    extern __shared__ char sm[];
    const int tid  = threadIdx.x;
    const int lane = tid & 31;
    const int wid  = tid >> 5;
    const int r0   = blockIdx.y * 128;
    const int n0   = blockIdx.x * 128;

    // ---- load A tile: rows r0..r0+127, all K=128; split bf16 hi/lo ----
    {
        int r  = tid >> 1;
        int c0 = (tid & 1) * 64;
        const float4* src = (const float4*)(Q + (size_t)(r0 + r) * D_DIM + c0);
        char* dhi = sm + SM_A_HI + r * SA_STR_B + c0 * 2;
        char* dlo = sm + SM_A_LO + r * SA_STR_B + c0 * 2;
        #pragma unroll
        for (int i = 0; i < 16; i++) {
            float4 v = src[i];
            float x[4] = {v.x, v.y, v.z, v.w};
            float hi[4], lo[4];
            #pragma unroll
            for (int j = 0; j < 4; j++) {
                hi[j] = __bfloat162float(__float2bfloat16(x[j]));
                lo[j] = x[j] - hi[j];
            }
            uint2 whi, wlo;
            whi.x = pack_bf16(hi[0], hi[1]); whi.y = pack_bf16(hi[2], hi[3]);
            wlo.x = pack_bf16(lo[0], lo[1]); wlo.y = pack_bf16(lo[2], lo[3]);
            *(uint2*)(dhi + i * 8) = whi;
            *(uint2*)(dlo + i * 8) = wlo;
        }
    }

    // ---- load B tile transposed: sB[n][k] = P[k][n0+n]; split hi/lo ----
    {
        int k  = tid >> 1;
        int c0 = (tid & 1) * 64;
        const float4* src = (const float4*)(P + (size_t)k * NPOS + n0 + c0);
        #pragma unroll
        for (int i = 0; i < 16; i++) {
            float4 v = src[i];
            float x[4] = {v.x, v.y, v.z, v.w};
            #pragma unroll
            for (int j = 0; j < 4; j++) {
                float hi = __bfloat162float(__float2bfloat16(x[j]));
                float lo = x[j] - hi;
                int n = c0 + i * 4 + j;
                *(__nv_bfloat16*)(sm + SM_B_HI + n * SA_STR_B + k * 2) = __float2bfloat16_rn(hi);
                *(__nv_bfloat16*)(sm + SM_B_LO + n * SA_STR_B + k * 2) = __float2bfloat16_rn(lo);
            }
        }
    }
    __syncthreads();

    // ---- main loop: 3 components x 8 k16-steps ----
    const int g = lane >> 2;          // 0..7
    const int t = lane & 3;           // 0..3
    const int mrow = (wid & 3) * 32;  // warp M offset in tile
    const int ncol = (wid >> 2) * 64; // warp N offset in tile

    float acc[2][8][4];
    #pragma unroll
    for (int mf = 0; mf < 2; mf++)
        #pragma unroll
        for (int nf = 0; nf < 8; nf++)
            #pragma unroll
            for (int c = 0; c < 4; c++) acc[mf][nf][c] = 0.0f;

    #pragma unroll
    for (int comp = 0; comp < 3; comp++) {
        const char* ab = sm + (comp == 2 ? SM_A_LO : SM_A_HI);
        const char* bb = sm + (comp == 1 ? SM_B_LO : SM_B_HI);
        #pragma unroll
        for (int ks = 0; ks < 8; ks++) {
            int kb = ks * 32 + t * 4;           // byte offset of k=ks*16 + t*2
            uint32_t a[2][4];
            #pragma unroll
            for (int mf = 0; mf < 2; mf++) {
                const char* base = ab + (mrow + mf * 16 + g) * SA_STR_B;
                a[mf][0] = *(const uint32_t*)(base + kb);
                a[mf][1] = *(const uint32_t*)(base + 8 * SA_STR_B + kb);
                a[mf][2] = *(const uint32_t*)(base + kb + 16);
                a[mf][3] = *(const uint32_t*)(base + 8 * SA_STR_B + kb + 16);
            }
            uint32_t b[8][2];
            #pragma unroll
            for (int nf = 0; nf < 8; nf++) {
                const char* base = bb + (ncol + nf * 8 + g) * SA_STR_B;
                b[nf][0] = *(const uint32_t*)(base + kb);
                b[nf][1] = *(const uint32_t*)(base + kb + 16);
            }
            #pragma unroll
            for (int mf = 0; mf < 2; mf++)
                #pragma unroll
                for (int nf = 0; nf < 8; nf++)
                    mma_bf16(acc[mf][nf], a[mf], b[nf]);
        }
    }

    // ---- epilogue ----
    #pragma unroll
    for (int mf = 0; mf < 2; mf++) {
        #pragma unroll
        for (int nf = 0; nf < 8; nf++) {
            float* p0 = g_logits
                + (size_t)(r0 + mrow + mf * 16 + g) * NPOS
                + n0 + ncol + nf * 8 + t * 2;
            *(float2*)p0 = make_float2(acc[mf][nf][0], acc[mf][nf][1]);
            *(float2*)(p0 + 8 * NPOS) = make_float2(acc[mf][nf][2], acc[mf][nf][3]);
        }
    }
}

// ============================================================================
// Kernel B: per (b,h,q) row — sigmoid, reversed cumsum, clamp, interp gather.
// float2-packed table: one LDS.64 per element instead of two LDS.32.
// ============================================================================
__global__ __launch_bounds__(256)
void cope_gather_kernel(const float* __restrict__ attn,   // [R,2048]
                        const int*   __restrict__ nposp,
                        float*       __restrict__ out) {  // [R,2048]
    __shared__ float  tabf[NPOS];
    __shared__ float2 tab2[NPOS];
    __shared__ float  wsum[8];

    const int row  = blockIdx.x;
    const int tid  = threadIdx.x;
    const int lane = tid & 31;
    const int wid  = tid >> 5;

    // stage this row's interpolation table
    const float* trow = g_logits + (size_t)row * NPOS;
    tabf[tid]       = trow[tid];
    tabf[tid + 256] = trow[tid + 256];
    __syncthreads();
    tab2[tid] = make_float2(tabf[tid], tabf[tid + 1]);
    {
        int i2 = tid + 256;
        tab2[i2] = make_float2(tabf[i2], (i2 == NPOS - 1) ? tabf[i2] : tabf[i2 + 1]);
    }

    // load 8 attn logits, sigmoid
    const float* arow = attn + (size_t)row * K_DIM + tid * 8;
    float4 v0 = *(const float4*)(arow);
    float4 v1 = *(const float4*)(arow + 4);
    float gg[8] = {v0.x, v0.y, v0.z, v0.w, v1.x, v1.y, v1.z, v1.w};
    #pragma unroll
    for (int j = 0; j < 8; j++)
        gg[j] = 1.0f / (1.0f + __expf(-gg[j]));

    // suffix cumsum inside the 8-element chunk
    float ls[8];
    ls[7] = gg[7];
    #pragma unroll
    for (int j = 6; j >= 0; j--) ls[j] = gg[j] + ls[j + 1];

    // warp inclusive scan of chunk totals
    float v = ls[0];
    #pragma unroll
    for (int d = 1; d < 32; d <<= 1) {
        float tt = __shfl_up_sync(0xffffffffu, v, d);
        if (lane >= d) v += tt;
    }
    if (lane == 31) wsum[wid] = v;
    __syncthreads();   // also makes tab2 visible

    float wpre = 0.0f, total = 0.0f;
    #pragma unroll
    for (int w = 0; w < 8; w++) {
        float x = wsum[w];
        total += x;
        if (w < wid) wpre += x;
    }
    float offset = total - (wpre + v);   // sum of all chunks AFTER this one

    const float npmf = (float)(*nposp - 1);

    float oo[8];
    #pragma unroll
    for (int j = 0; j < 8; j++) {
        float p  = fminf(offset + ls[j], npmf);
        float pf = floorf(p);
        float w  = p - pf;
        float2 tt = tab2[(int)pf];
        oo[j] = fmaf(w, tt.y - tt.x, tt.x);
    }

    float* orow = out + (size_t)row * K_DIM + tid * 8;
    *(float4*)(orow)     = make_float4(oo[0], oo[1], oo[2], oo[3]);
    *(float4*)(orow + 4) = make_float4(oo[4], oo[5], oo[6], oo[7]);
}

// ---------------------------------------------------------------------------
extern "C" void kernel_launch(void* const* d_in, const int* in_sizes, int n_in,
                              void* d_out, int out_size) {
    const float* q    = (const float*)d_in[0];   // [B,H,Q,D]
    const float* attn = (const float*)d_in[1];   // [B,H,Q,K]
    const float* pe   = (const float*)d_in[2];   // [1,D,NPOS]
    const int*   npos = (const int*)d_in[3];
    float*       out  = (float*)d_out;

    const int R = in_sizes[0] / D_DIM;           // 49152

    cudaFuncSetAttribute(cope_gemm_mma,
                         cudaFuncAttributeMaxDynamicSharedMemorySize, SM_TOTAL);
    dim3 gA(NPOS / 128, R / 128);
    cope_gemm_mma<<<gA, 256, SM_TOTAL>>>(q, pe);

    cope_gather_kernel<<<R, 256>>>(attn, npos, out);

    (void)n_in; (void)out_size;
}

// round 4
// speedup vs baseline: 2.2314x; 1.0677x over previous
#include <cuda_runtime.h>
#include <cuda_bf16.h>
#include <cuda_fp16.h>
#include <cstdint>

#define D_DIM   128
#define NPOS    512
#define K_DIM   2048
#define R_MAX   49152    // B*H*Q = 2*12*2048

// 50 MB scratch: fp16 interpolation tables (512 entries per (b,h,q) row).
__device__ __half g_table[(size_t)R_MAX * NPOS];

// ---------------------------------------------------------------------------
// mma.sync m16n8k16 row.col f32.bf16.bf16.f32  (tensor pipe, sm_80+ PTX)
// ---------------------------------------------------------------------------
__device__ __forceinline__ void mma_bf16(float* d, const uint32_t* a, const uint32_t* b) {
    asm volatile(
        "mma.sync.aligned.m16n8k16.row.col.f32.bf16.bf16.f32 "
        "{%0,%1,%2,%3}, {%4,%5,%6,%7}, {%8,%9}, {%0,%1,%2,%3};"
        : "+f"(d[0]), "+f"(d[1]), "+f"(d[2]), "+f"(d[3])
        : "r"(a[0]), "r"(a[1]), "r"(a[2]), "r"(a[3]), "r"(b[0]), "r"(b[1]));
}

__device__ __forceinline__ void ldsm_x4(uint32_t* r, uint32_t addr) {
    asm volatile("ldmatrix.sync.aligned.m8n8.x4.shared.b16 {%0,%1,%2,%3}, [%4];"
        : "=r"(r[0]), "=r"(r[1]), "=r"(r[2]), "=r"(r[3]) : "r"(addr));
}
__device__ __forceinline__ void ldsm_x4_t(uint32_t* r, uint32_t addr) {
    asm volatile("ldmatrix.sync.aligned.m8n8.x4.trans.shared.b16 {%0,%1,%2,%3}, [%4];"
        : "=r"(r[0]), "=r"(r[1]), "=r"(r[2]), "=r"(r[3]) : "r"(addr));
}

__device__ __forceinline__ uint32_t smem_u32(const void* p) {
    uint32_t a;
    asm("{ .reg .u64 t; cvta.to.shared.u64 t, %1; cvt.u32.u64 %0, t; }" : "=r"(a) : "l"(p));
    return a;
}

__device__ __forceinline__ uint32_t pack_bf16(float a, float b) {
    __nv_bfloat162 t = __floats2bfloat162_rn(a, b);
    return *reinterpret_cast<uint32_t*>(&t);
}

// ============================================================================
// Kernel A: T[R,512] = Q[R,128] @ P[128,512], bf16x3 split, merged-comp loop.
// Block 128x128 tile, 8 warps (4M x 2N), warp tile m32 x n64.
// A tiles [m][k] (stride 272 B), B tiles [k][n] (stride 272 B, k-major).
// ldmatrix (A) / ldmatrix.trans (B); epilogue writes half2 pairs to g_table.
// ============================================================================
#define SSTR      272           // smem row stride in bytes
#define SM_A_HI   0
#define SM_A_LO   34816         // 128*272
#define SM_B_HI   69632
#define SM_B_LO   104448
#define SM_TOTAL  139264

__global__ __launch_bounds__(256, 1)
void cope_gemm_mma(const float* __restrict__ Q,   // [R,128]
                   const float* __restrict__ P) { // [128,512]
    extern __shared__ char sm[];
    const int tid  = threadIdx.x;
    const int lane = tid & 31;
    const int wid  = tid >> 5;
    const int r0   = blockIdx.y * 128;
    const int n0   = blockIdx.x * 128;

    // ---- load A tile: 128 rows x K=128, split bf16 hi/lo, [m][k] ----
    {
        int r  = tid >> 1;
        int c0 = (tid & 1) * 64;
        const float4* src = (const float4*)(Q + (size_t)(r0 + r) * D_DIM + c0);
        char* dhi = sm + SM_A_HI + r * SSTR + c0 * 2;
        char* dlo = sm + SM_A_LO + r * SSTR + c0 * 2;
        #pragma unroll
        for (int i = 0; i < 16; i++) {
            float4 v = src[i];
            float x[4] = {v.x, v.y, v.z, v.w};
            float hi[4], lo[4];
            #pragma unroll
            for (int j = 0; j < 4; j++) {
                hi[j] = __bfloat162float(__float2bfloat16(x[j]));
                lo[j] = x[j] - hi[j];
            }
            uint2 whi, wlo;
            whi.x = pack_bf16(hi[0], hi[1]); whi.y = pack_bf16(hi[2], hi[3]);
            wlo.x = pack_bf16(lo[0], lo[1]); wlo.y = pack_bf16(lo[2], lo[3]);
            *(uint2*)(dhi + i * 8) = whi;
            *(uint2*)(dlo + i * 8) = wlo;
        }
    }

    // ---- load B tile k-major: sB[k][n] = P[k][n0+n], split hi/lo ----
    {
        int k  = tid >> 1;
        int c0 = (tid & 1) * 64;
        const float4* src = (const float4*)(P + (size_t)k * NPOS + n0 + c0);
        char* dhi = sm + SM_B_HI + k * SSTR + c0 * 2;
        char* dlo = sm + SM_B_LO + k * SSTR + c0 * 2;
        #pragma unroll
        for (int i = 0; i < 16; i++) {
            float4 v = src[i];
            float x[4] = {v.x, v.y, v.z, v.w};
            float hi[4], lo[4];
            #pragma unroll
            for (int j = 0; j < 4; j++) {
                hi[j] = __bfloat162float(__float2bfloat16(x[j]));
                lo[j] = x[j] - hi[j];
            }
            uint2 whi, wlo;
            whi.x = pack_bf16(hi[0], hi[1]); whi.y = pack_bf16(hi[2], hi[3]);
            wlo.x = pack_bf16(lo[0], lo[1]); wlo.y = pack_bf16(lo[2], lo[3]);
            *(uint2*)(dhi + i * 8) = whi;
            *(uint2*)(dlo + i * 8) = wlo;
        }
    }
    __syncthreads();

    const int g = lane >> 2;           // 0..7
    const int t = lane & 3;            // 0..3
    const int mrow = (wid & 3) * 32;
    const int ncol = (wid >> 2) * 64;

    // ldmatrix per-lane address components
    const uint32_t smb = smem_u32(sm);
    // A: matrix i=lane>>3: rows mrow+mf*16+(i&1)*8+(lane&7), col byte kb+(i>>1)*16
    const uint32_t a_off = (uint32_t)((mrow + ((lane >> 3) & 1) * 8 + (lane & 7)) * SSTR
                                      + (lane >> 4) * 16);
    // B(trans): matrix i: k-rows ks*16+(i&1)*8+(lane&7), col byte ncol*2+p*32+(i>>1)*16
    const uint32_t b_off = (uint32_t)((((lane >> 3) & 1) * 8 + (lane & 7)) * SSTR
                                      + (lane >> 4) * 16 + ncol * 2);

    float acc[2][8][4];
    #pragma unroll
    for (int mf = 0; mf < 2; mf++)
        #pragma unroll
        for (int nf = 0; nf < 8; nf++)
            #pragma unroll
            for (int c = 0; c < 4; c++) acc[mf][nf][c] = 0.0f;

    #pragma unroll
    for (int ks = 0; ks < 8; ks++) {
        const uint32_t kb = ks * 32;               // byte offset along k
        uint32_t ahi[2][4], alo[2][4];
        #pragma unroll
        for (int mf = 0; mf < 2; mf++) {
            ldsm_x4(ahi[mf], smb + SM_A_HI + mf * 16 * SSTR + a_off + kb);
            ldsm_x4(alo[mf], smb + SM_A_LO + mf * 16 * SSTR + a_off + kb);
        }
        uint32_t bhi[4][4], blo[4][4];             // p covers nf=2p, 2p+1
        #pragma unroll
        for (int p = 0; p < 4; p++) {
            ldsm_x4_t(bhi[p], smb + SM_B_HI + ks * 16 * SSTR + b_off + p * 32);
            ldsm_x4_t(blo[p], smb + SM_B_LO + ks * 16 * SSTR + b_off + p * 32);
        }
        #pragma unroll
        for (int mf = 0; mf < 2; mf++) {
            #pragma unroll
            for (int p = 0; p < 4; p++) {
                mma_bf16(acc[mf][2 * p],     ahi[mf], &bhi[p][0]);  // Ahi*Bhi
                mma_bf16(acc[mf][2 * p + 1], ahi[mf], &bhi[p][2]);
                mma_bf16(acc[mf][2 * p],     ahi[mf], &blo[p][0]);  // Ahi*Blo
                mma_bf16(acc[mf][2 * p + 1], ahi[mf], &blo[p][2]);
                mma_bf16(acc[mf][2 * p],     alo[mf], &bhi[p][0]);  // Alo*Bhi
                mma_bf16(acc[mf][2 * p + 1], alo[mf], &bhi[p][2]);
            }
        }
    }

    // ---- epilogue: pack (c0,c1)/(c2,c3) column pairs as half2 ----
    #pragma unroll
    for (int mf = 0; mf < 2; mf++) {
        #pragma unroll
        for (int nf = 0; nf < 8; nf++) {
            size_t row = (size_t)(r0 + mrow + mf * 16 + g);
            size_t nn  = (size_t)(n0 + ncol + nf * 8 + t * 2);
            __half2 h0 = __floats2half2_rn(acc[mf][nf][0], acc[mf][nf][1]);
            __half2 h1 = __floats2half2_rn(acc[mf][nf][2], acc[mf][nf][3]);
            *(uint32_t*)(g_table + row * NPOS + nn)        = *(uint32_t*)&h0;
            *(uint32_t*)(g_table + (row + 8) * NPOS + nn)  = *(uint32_t*)&h1;
        }
    }
}

// ============================================================================
// Kernel B: per row — sigmoid, reversed cumsum, clamp, interp gather.
// Table staged as half2 pairs (t[i], t[i+1]) -> one LDS.32 per element.
// ============================================================================
__global__ __launch_bounds__(256)
void cope_gather_kernel(const float* __restrict__ attn,   // [R,2048]
                        const int*   __restrict__ nposp,
                        float*       __restrict__ out) {  // [R,2048]
    __shared__ __half    tabh[NPOS];
    __shared__ uint32_t  tab2u[NPOS];
    __shared__ float     wsum[8];

    const int row  = blockIdx.x;
    const int tid  = threadIdx.x;
    const int lane = tid & 31;
    const int wid  = tid >> 5;

    // stage this row's fp16 table (256 x LDG.32 covers 512 halves)
    ((uint32_t*)tabh)[tid] =
        ((const uint32_t*)(g_table + (size_t)row * NPOS))[tid];

    // load 8 attn logits, sigmoid
    const float* arow = attn + (size_t)row * K_DIM + tid * 8;
    float4 v0 = *(const float4*)(arow);
    float4 v1 = *(const float4*)(arow + 4);
    float gg[8] = {v0.x, v0.y, v0.z, v0.w, v1.x, v1.y, v1.z, v1.w};
    #pragma unroll
    for (int j = 0; j < 8; j++)
        gg[j] = 1.0f / (1.0f + __expf(-gg[j]));

    __syncthreads();
    // build interpolation pairs: tab2u[i] = half2(t[i], t[i+1])
    {
        __half a = tabh[tid], b = tabh[tid + 1];
        __half2 h; h.x = a; h.y = b;
        tab2u[tid] = *(uint32_t*)&h;
        int i2 = tid + 256;
        __half a2 = tabh[i2];
        __half b2 = (i2 == NPOS - 1) ? a2 : tabh[i2 + 1];
        __half2 h2; h2.x = a2; h2.y = b2;
        tab2u[i2] = *(uint32_t*)&h2;
    }

    // suffix cumsum inside the 8-element chunk
    float ls[8];
    ls[7] = gg[7];
    #pragma unroll
    for (int j = 6; j >= 0; j--) ls[j] = gg[j] + ls[j + 1];

    // warp inclusive scan of chunk totals
    float v = ls[0];
    #pragma unroll
    for (int d = 1; d < 32; d <<= 1) {
        float tt = __shfl_up_sync(0xffffffffu, v, d);
        if (lane >= d) v += tt;
    }
    if (lane == 31) wsum[wid] = v;
    __syncthreads();   // covers tab2u + wsum

    float wpre = 0.0f, total = 0.0f;
    #pragma unroll
    for (int w = 0; w < 8; w++) {
        float x = wsum[w];
        total += x;
        if (w < wid) wpre += x;
    }
    float offset = total - (wpre + v);   // sum of chunks AFTER this one

    const float npmf = (float)(*nposp - 1);

    float oo[8];
    #pragma unroll
    for (int j = 0; j < 8; j++) {
        float p  = fminf(offset + ls[j], npmf);
        float pf = floorf(p);
        float w  = p - pf;
        uint32_t pv = tab2u[(int)pf];
        float2 f = __half22float2(*(__half2*)&pv);
        oo[j] = fmaf(w, f.y - f.x, f.x);
    }

    float* orow = out + (size_t)row * K_DIM + tid * 8;
    *(float4*)(orow)     = make_float4(oo[0], oo[1], oo[2], oo[3]);
    *(float4*)(orow + 4) = make_float4(oo[4], oo[5], oo[6], oo[7]);
}

// ---------------------------------------------------------------------------
extern "C" void kernel_launch(void* const* d_in, const int* in_sizes, int n_in,
                              void* d_out, int out_size) {
    const float* q    = (const float*)d_in[0];   // [B,H,Q,D]
    const float* attn = (const float*)d_in[1];   // [B,H,Q,K]
    const float* pe   = (const float*)d_in[2];   // [1,D,NPOS]
    const int*   npos = (const int*)d_in[3];
    float*       out  = (float*)d_out;

    const int R = in_sizes[0] / D_DIM;           // 49152

    cudaFuncSetAttribute(cope_gemm_mma,
                         cudaFuncAttributeMaxDynamicSharedMemorySize, SM_TOTAL);
    dim3 gA(NPOS / 128, R / 128);
    cope_gemm_mma<<<gA, 256, SM_TOTAL>>>(q, pe);

    cope_gather_kernel<<<R, 256>>>(attn, npos, out);

    (void)n_in; (void)out_size;
}